// round 5
// baseline (speedup 1.0000x reference)
#include <cuda_runtime.h>
#include <math.h>

// RoI max pooling (Caffe-style), bit-matching the JAX/XLA reference.
//   x    : [B=2, C=128, H=64, W=64] fp32
//   rois : [N=256, 5]  (batch_idx, x1, y1, x2, y2) image coords
//   out  : [N, C, 7, 7] fp32
//
// Two-kernel plan: bin boundaries depend only on (n, ph, pw) — computing
// them per output element is 128x redundant ALU (the R4 profile showed
// alu+fma = 39% of issue on that redundancy). Kernel A computes the 12544
// bin records once; kernel B does the pure gather/max with coalesced
// bounds loads and coalesced stores.
//
// CRITICAL (bit-exactness): XLA rewrites `roi / 7` into `roi * fl32(1/7)`.
// We must use the same reciprocal multiply or floor/ceil boundaries shift
// by 1 ulp on 7-divisible roi extents (caused rel_err 9.6e-2 in R1/R3).

#define B_  2
#define C_  128
#define H_  64
#define W_  64
#define N_  256
#define OUTH_ 7
#define OUTW_ 7
#define NBINS_ (N_ * OUTH_ * OUTW_)   // 12544
#define SCALE_ (1.0f / 16.0f)
#define RCP7_  (1.0f / 7.0f)          // fp32 RN: 0x3E124925

// scratch (static device globals — no allocation)
__device__ int4 g_bounds[NBINS_];   // {hstart, hend, wstart, wend} clamped
__device__ int  g_bidx[N_];         // batch index per roi

__global__ void roi_bounds_kernel(const float* __restrict__ rois) {
    int tid = blockIdx.x * blockDim.x + threadIdx.x;
    if (tid >= NBINS_) return;

    const int k  = tid % (OUTH_ * OUTW_);
    const int n  = tid / (OUTH_ * OUTW_);
    const int pw = k % OUTW_;
    const int ph = k / OUTW_;

    const float* r = rois + n * 5;
    const int xs = (int)rintf(r[1] * SCALE_);
    const int ys = (int)rintf(r[2] * SCALE_);
    const int xe = (int)rintf(r[3] * SCALE_);
    const int ye = (int)rintf(r[4] * SCALE_);

    const float roi_w = (float)max(xe - xs + 1, 1);
    const float roi_h = (float)max(ye - ys + 1, 1);
    // match XLA's divide -> multiply-by-reciprocal rewrite exactly
    const float bin_h = __fmul_rn(roi_h, RCP7_);
    const float bin_w = __fmul_rn(roi_w, RCP7_);

    int hstart = (int)floorf(__fmul_rn((float)ph, bin_h)) + ys;
    int hend   = (int)ceilf(__fmul_rn((float)ph + 1.0f, bin_h)) + ys;
    int wstart = (int)floorf(__fmul_rn((float)pw, bin_w)) + xs;
    int wend   = (int)ceilf(__fmul_rn((float)pw + 1.0f, bin_w)) + xs;
    hstart = min(max(hstart, 0), H_);
    hend   = min(max(hend,   0), H_);
    wstart = min(max(wstart, 0), W_);
    wend   = min(max(wend,   0), W_);

    g_bounds[tid] = make_int4(hstart, hend, wstart, wend);
    if (k == 0) g_bidx[n] = (int)r[0];
}

__global__ void roi_pool_kernel(const float* __restrict__ x,
                                float* __restrict__ out) {
    const int total = N_ * C_ * OUTH_ * OUTW_;
    int idx = blockIdx.x * blockDim.x + threadIdx.x;
    if (idx >= total) return;

    // idx = ((n*C + c) * 49) + bin  ; bin = ph*7+pw
    const int bin = idx % (OUTH_ * OUTW_);
    const int nc  = idx / (OUTH_ * OUTW_);
    const int n   = nc / C_;
    const int c   = nc % C_;

    const int4 b = g_bounds[n * (OUTH_ * OUTW_) + bin];  // coalesced per warp
    const int bidx = g_bidx[n];                          // broadcast

    const float* plane = x + ((size_t)bidx * C_ + c) * (H_ * W_);

    const bool empty = (b.y <= b.x) || (b.w <= b.z);

    float maxval = -INFINITY;
    for (int h = b.x; h < b.y; ++h) {
        const float* row = plane + h * W_;
        #pragma unroll 4
        for (int w = b.z; w < b.w; ++w) {
            maxval = fmaxf(maxval, __ldg(row + w));
        }
    }

    out[idx] = empty ? 0.0f : maxval;
}

extern "C" void kernel_launch(void* const* d_in, const int* in_sizes, int n_in,
                              void* d_out, int out_size) {
    const float* x    = (const float*)d_in[0];
    const float* rois = (const float*)d_in[1];
    float* out = (float*)d_out;

    const int threads = 256;
    roi_bounds_kernel<<<(NBINS_ + threads - 1) / threads, threads>>>(rois);

    const int total = N_ * C_ * OUTH_ * OUTW_;
    roi_pool_kernel<<<(total + threads - 1) / threads, threads>>>(x, out);
}